// round 7
// baseline (speedup 1.0000x reference)
#include <cuda_runtime.h>
#include <cuda_bf16.h>
#include <cstdint>

// CTC loss, FUSED single kernel. One block (8 warps) per batch row.
// Phase 1: warps 0..7 softmax their 32-timestep slice, store compact
//   normalized probs in SHARED memory (labels t-paired bfloat162 + blanks).
// Phase 2: warp 0 runs the serial alpha recursion from shared; warps 1..7 exit.
// B=2048, T=256, C=128, L=32, S=65.
#define T_DIM 256
#define C_DIM 128
#define L_DIM 32
#define NW    8

__global__ __launch_bounds__(NW * 32)
void ctc_fused(const int* __restrict__ y_true,
               const float* __restrict__ y_pred,
               float* __restrict__ out, int B)
{
    __shared__ float         esc[NW][4][C_DIM];        // 16 KB exp scratch
    __shared__ unsigned      sm_lab[T_DIM / 2][L_DIM]; // 16 KB: (p_t, p_{t+1}) per label
    __shared__ __nv_bfloat16 sm_bl[T_DIM];             // 0.5 KB: blank probs

    const int tid  = threadIdx.x;
    const int w    = tid >> 5;
    const int lane = tid & 31;
    const int b    = blockIdx.x;
    const unsigned FULL = 0xffffffffu;
    if (b >= B) return;

    // lane l <-> label index l (class), previous label via shuffle
    const int labl = y_true[b * L_DIM + lane];
    const int labp = __shfl_up_sync(FULL, labl, 1);

    const float4* rp =
        reinterpret_cast<const float4*>(y_pred + (size_t)b * T_DIM * C_DIM);

    // ---------------- phase 1: warp w covers t in [32w, 32w+32) -------------
    for (int i = 0; i < 8; ++i) {
        const int t0 = w * 32 + i * 4;

        float4 x[4];
#pragma unroll
        for (int j = 0; j < 4; ++j)
            x[j] = rp[(size_t)(t0 + j) * 32 + lane];   // 4 loads in flight

        float d[4], ez[4];
#pragma unroll
        for (int j = 0; j < 4; ++j) {
            float e0 = __expf(x[j].x), e1 = __expf(x[j].y);
            float e2 = __expf(x[j].z), e3 = __expf(x[j].w);
            reinterpret_cast<float4*>(esc[w][j])[lane] = make_float4(e0, e1, e2, e3);
            d[j]  = (e0 + e1) + (e2 + e3);
            ez[j] = e0;                                 // lane0: exp at class 0
        }
#pragma unroll
        for (int o = 16; o > 0; o >>= 1)
#pragma unroll
            for (int j = 0; j < 4; ++j)
                d[j] += __shfl_xor_sync(FULL, d[j], o);
        __syncwarp();                                   // esc visible to warp

        float inv[4];
#pragma unroll
        for (int j = 0; j < 4; ++j) inv[j] = __fdividef(1.0f, d[j]);

        float p[4];
#pragma unroll
        for (int j = 0; j < 4; ++j) p[j] = esc[w][j][labl] * inv[j];

        __nv_bfloat162 p01 = __floats2bfloat162_rn(p[0], p[1]);
        __nv_bfloat162 p23 = __floats2bfloat162_rn(p[2], p[3]);
        sm_lab[t0 / 2][lane]     = *reinterpret_cast<unsigned*>(&p01);
        sm_lab[t0 / 2 + 1][lane] = *reinterpret_cast<unsigned*>(&p23);

        if (lane == 0) {
            __nv_bfloat162 b01 = __floats2bfloat162_rn(ez[0] * inv[0], ez[1] * inv[1]);
            __nv_bfloat162 b23 = __floats2bfloat162_rn(ez[2] * inv[2], ez[3] * inv[3]);
            uint2 pk;
            pk.x = *reinterpret_cast<unsigned*>(&b01);
            pk.y = *reinterpret_cast<unsigned*>(&b23);
            *reinterpret_cast<uint2*>(&sm_bl[t0]) = pk;
        }
        __syncwarp();   // gathers done before next iteration overwrites esc
    }
    __syncthreads();
    if (w != 0) return;             // free 7 warps' scheduler slots

    // ---------------- phase 2: warp 0, serial recursion from smem -----------
    // lane l owns states 2l (blank) and 2l+1 (label l); s=64 lives on lane 31.
    const float m0 = (lane == 0) ? 0.f : 1.f;
    const float sk = (lane >= 1 && labl != labp) ? 1.f : 0.f;

    float a_e = (lane == 0) ? 1.f : 0.f;   // virtual alpha_{-1} = delta(s=0)
    float a_o = 0.f;
    float a64 = 0.f;                        // alpha[64], valid on lane 31
    float acc = 0.f;

    for (int tb = 0; tb < T_DIM; tb += 8) {
        uint4 bw = *reinterpret_cast<const uint4*>(&sm_bl[tb]);   // 8 blanks
        const __nv_bfloat16* bp = reinterpret_cast<const __nv_bfloat16*>(&bw);

#pragma unroll
        for (int u = 0; u < 4; ++u) {
            unsigned lw = sm_lab[tb / 2 + u][lane];
            float2 pr = __bfloat1622float2(*reinterpret_cast<__nv_bfloat162*>(&lw));
#pragma unroll
            for (int h = 0; h < 2; ++h) {
                float pl = h ? pr.y : pr.x;
                float bt = __bfloat162float(bp[2 * u + h]);

                float um = __shfl_up_sync(FULL, a_o, 1) * m0;  // alpha[2l-1]
                float ae_n = (a_e + um) * bt;
                float ao_n = ((a_o + a_e) + sk * um) * pl;
                a64 = (a64 + a_o) * bt;        // lane 31: alpha[63] = own a_o
                a_e = ae_n; a_o = ao_n;
            }
        }
        // renormalize every 8 steps (alpha shrinks ~(3/128)^8)
        float ps = a_e + a_o + ((lane == 31) ? a64 : 0.f);
#pragma unroll
        for (int o = 16; o > 0; o >>= 1)
            ps += __shfl_xor_sync(FULL, ps, o);
        float r = __fdividef(1.0f, ps);
        a_e *= r; a_o *= r; a64 *= r;
        acc += __logf(ps);
    }

    if (lane == 31)
        out[b] = -(__logf(a_o + a64) + acc);   // alpha[63] + alpha[64]
}

extern "C" void kernel_launch(void* const* d_in, const int* in_sizes, int n_in,
                              void* d_out, int out_size)
{
    const int B = out_size;
    const int*   y_true;
    const float* y_pred;
    if (in_sizes[0] < in_sizes[1]) {       // labels buffer is the smaller one
        y_true = (const int*)d_in[0];
        y_pred = (const float*)d_in[1];
    } else {
        y_true = (const int*)d_in[1];
        y_pred = (const float*)d_in[0];
    }
    float* outp = (float*)d_out;

    ctc_fused<<<B, NW * 32>>>(y_true, y_pred, outp, B);
}

// round 8
// speedup vs baseline: 1.0267x; 1.0267x over previous
#include <cuda_runtime.h>
#include <cuda_bf16.h>
#include <cstdint>

// CTC loss: single kernel, grid-scale producer/consumer overlap.
// Producers (blocks 0..B-1), chunk-major over T: block = (chunk, 8 rows),
//   warp = one row's 32-timestep chunk: softmax over C=128, write compact
//   bf16 probs (labels t-paired + blanks) to global, release a flag.
// Consumers (blocks B..B+B/8-1): warp = one row; per chunk acquire the flag,
//   run 32 steps of the alpha recursion (lane l owns states 2l, 2l+1).
// B=2048, T=256, C=128, L=32, S=65.
#define T_DIM  256
#define C_DIM  128
#define L_DIM  32
#define MAXB   2048
#define NCHUNK 8
#define CT     32            // timesteps per chunk
#define PW     8             // warps per block (both roles)

__device__ unsigned      g_lab[(size_t)MAXB * (T_DIM / 2) * L_DIM]; // t-paired label probs
__device__ __nv_bfloat16 g_blank[(size_t)MAXB * T_DIM];             // blank probs
__device__ int           g_flag[MAXB * NCHUNK];                     // zero-init

__device__ __forceinline__ int ldacq_g(const int* p) {
    int v;
    asm volatile("ld.acquire.gpu.global.b32 %0, [%1];" : "=r"(v) : "l"(p) : "memory");
    return v;
}
__device__ __forceinline__ void strel_g(int* p, int v) {
    asm volatile("st.release.gpu.global.b32 [%0], %1;" :: "l"(p), "r"(v) : "memory");
}

__global__ __launch_bounds__(PW * 32)
void ctc_pc(const int* __restrict__ y_true,
            const float* __restrict__ y_pred,
            float* __restrict__ out, int B)
{
    __shared__ float esc[PW][4][C_DIM];     // 16 KB exp scratch (producers only)

    const int bid  = blockIdx.x;
    const int tid  = threadIdx.x;
    const int w    = tid >> 5;
    const int lane = tid & 31;
    const unsigned FULL = 0xffffffffu;

    if (bid < B) {
        // ================= PRODUCER =================
        const int c  = bid / (B >> 3);               // chunk 0..7 (chunk-major)
        const int r  = (bid % (B >> 3)) * 8 + w;     // this warp's row
        const int t0 = c * CT;

        const int labl = __ldg(&y_true[r * L_DIM + lane]);
        const float4* rp =
            reinterpret_cast<const float4*>(y_pred + (size_t)r * T_DIM * C_DIM);
        unsigned* gl = g_lab + (size_t)r * (T_DIM / 2) * L_DIM;

        for (int i = 0; i < 8; ++i) {                // 4 timesteps per iter
            const int tt = t0 + i * 4;

            float4 x[4];
#pragma unroll
            for (int j = 0; j < 4; ++j)
                x[j] = rp[(size_t)(tt + j) * 32 + lane];   // 4 loads in flight

            float d[4], ez[4];
#pragma unroll
            for (int j = 0; j < 4; ++j) {
                float e0 = __expf(x[j].x), e1 = __expf(x[j].y);
                float e2 = __expf(x[j].z), e3 = __expf(x[j].w);
                reinterpret_cast<float4*>(esc[w][j])[lane] =
                    make_float4(e0, e1, e2, e3);
                d[j]  = (e0 + e1) + (e2 + e3);
                ez[j] = e0;                          // lane0: exp(class 0)
            }
#pragma unroll
            for (int o = 16; o > 0; o >>= 1)
#pragma unroll
                for (int j = 0; j < 4; ++j)
                    d[j] += __shfl_xor_sync(FULL, d[j], o);
            __syncwarp();

            float inv[4], p[4];
#pragma unroll
            for (int j = 0; j < 4; ++j) inv[j] = __fdividef(1.0f, d[j]);
#pragma unroll
            for (int j = 0; j < 4; ++j) p[j] = esc[w][j][labl] * inv[j];

            __nv_bfloat162 p01 = __floats2bfloat162_rn(p[0], p[1]);
            __nv_bfloat162 p23 = __floats2bfloat162_rn(p[2], p[3]);
            gl[(size_t)(tt >> 1) * L_DIM + lane]       = *reinterpret_cast<unsigned*>(&p01);
            gl[(size_t)((tt >> 1) + 1) * L_DIM + lane] = *reinterpret_cast<unsigned*>(&p23);

            if (lane == 0) {
                __nv_bfloat162 b01 = __floats2bfloat162_rn(ez[0] * inv[0], ez[1] * inv[1]);
                __nv_bfloat162 b23 = __floats2bfloat162_rn(ez[2] * inv[2], ez[3] * inv[3]);
                uint2 pk;
                pk.x = *reinterpret_cast<unsigned*>(&b01);
                pk.y = *reinterpret_cast<unsigned*>(&b23);
                *reinterpret_cast<uint2*>(&g_blank[(size_t)r * T_DIM + tt]) = pk;
            }
            __syncwarp();            // gathers done before esc overwritten
        }
        __syncwarp();
        __threadfence();             // order this warp's prob stores
        if (lane == 0) strel_g(&g_flag[r * NCHUNK + c], 1);
        return;
    }

    // ================= CONSUMER =================
    const int r = (bid - B) * 8 + w;                  // one row per warp
    if (r >= B) return;

    const int labl = __ldg(&y_true[r * L_DIM + lane]);
    const int labp = __shfl_up_sync(FULL, labl, 1);
    const float m0 = (lane == 0) ? 0.f : 1.f;
    const float sk = (lane >= 1 && labl != labp) ? 1.f : 0.f;

    const unsigned* gl       = g_lab + (size_t)r * (T_DIM / 2) * L_DIM;
    const __nv_bfloat16* gb  = g_blank + (size_t)r * T_DIM;
    const int* fl            = &g_flag[r * NCHUNK];

    float a_e = (lane == 0) ? 1.f : 0.f;   // virtual alpha_{-1} = delta(s=0)
    float a_o = 0.f;
    float a64 = 0.f;                        // alpha[64], lives on lane 31
    float acc = 0.f;

    for (int c = 0; c < NCHUNK; ++c) {
        while (ldacq_g(fl + c) == 0) __nanosleep(64);

        // sub-blocks of 8 timesteps, double-buffered loads
        unsigned pcur[4]; uint4 bcur;
#pragma unroll
        for (int u = 0; u < 4; ++u) pcur[u] = gl[(size_t)(c * 16 + u) * L_DIM + lane];
        bcur = *reinterpret_cast<const uint4*>(gb + c * CT);

#pragma unroll
        for (int sb = 0; sb < 4; ++sb) {
            unsigned pnxt[4]; uint4 bnxt;
            if (sb < 3) {
#pragma unroll
                for (int u = 0; u < 4; ++u)
                    pnxt[u] = gl[(size_t)(c * 16 + (sb + 1) * 4 + u) * L_DIM + lane];
                bnxt = *reinterpret_cast<const uint4*>(gb + c * CT + (sb + 1) * 8);
            }

            const __nv_bfloat16* bp =
                reinterpret_cast<const __nv_bfloat16*>(&bcur);
#pragma unroll
            for (int u = 0; u < 4; ++u) {
                float2 pr = __bfloat1622float2(
                    *reinterpret_cast<__nv_bfloat162*>(&pcur[u]));
#pragma unroll
                for (int h = 0; h < 2; ++h) {
                    float pl = h ? pr.y : pr.x;
                    float bt = __bfloat162float(bp[2 * u + h]);

                    float um = __shfl_up_sync(FULL, a_o, 1) * m0;  // alpha[2l-1]
                    float ae_n = (a_e + um) * bt;
                    float ao_n = ((a_o + a_e) + sk * um) * pl;
                    a64 = (a64 + a_o) * bt;        // lane31: old a_o = alpha[63]
                    a_e = ae_n; a_o = ao_n;
                }
            }
            // renormalize every 8 steps
            float ps = a_e + a_o + ((lane == 31) ? a64 : 0.f);
#pragma unroll
            for (int o = 16; o > 0; o >>= 1)
                ps += __shfl_xor_sync(FULL, ps, o);
            float rr = __fdividef(1.0f, ps);
            a_e *= rr; a_o *= rr; a64 *= rr;
            acc += __logf(ps);

            if (sb < 3) {
#pragma unroll
                for (int u = 0; u < 4; ++u) pcur[u] = pnxt[u];
                bcur = bnxt;
            }
        }
    }

    if (lane == 31)
        out[r] = -(__logf(a_o + a64) + acc);   // alpha[63] + alpha[64]
}

extern "C" void kernel_launch(void* const* d_in, const int* in_sizes, int n_in,
                              void* d_out, int out_size)
{
    const int B = out_size;
    const int*   y_true;
    const float* y_pred;
    if (in_sizes[0] < in_sizes[1]) {       // labels buffer is the smaller one
        y_true = (const int*)d_in[0];
        y_pred = (const float*)d_in[1];
    } else {
        y_true = (const int*)d_in[1];
        y_pred = (const float*)d_in[0];
    }
    float* outp = (float*)d_out;

    const int nprod = B;
    const int ncons = (B + 7) / 8;
    ctc_pc<<<nprod + ncons, PW * 32>>>(y_true, y_pred, outp, B);
}

// round 11
// speedup vs baseline: 1.0904x; 1.0620x over previous
#include <cuda_runtime.h>
#include <cuda_bf16.h>
#include <cstdint>

// CTC loss, two-pass.
// Pass 1 (unchanged from best round): warp per 4 timesteps, softmax C=128,
//   compact bf16 probs: labels t-paired [b][t/2][32], blanks [b][t].
// Pass 2: warp per row, BIDIRECTIONAL: alpha t=0..127 and beta t=255..128
//   interleaved in one warp (independent chains hide each other's latency).
//   loss = -log( sum_s alphapre_128[s] * beta_128[s] ) - renorm logs.
#define T_DIM 256
#define C_DIM 128
#define L_DIM 32
#define MAXB  2048
#define P1W   8
#define WPB2  4

__device__ unsigned      g_lab[(size_t)MAXB * (T_DIM / 2) * L_DIM];
__device__ __nv_bfloat16 g_blank[(size_t)MAXB * T_DIM];

// ---------------- pass 1 (identical to round-6 version) ---------------------
__global__ __launch_bounds__(P1W * 32)
void ctc_pass1(const int* __restrict__ y_true,
               const float* __restrict__ y_pred, int BT4)
{
    __shared__ float esc[P1W][4][C_DIM];

    const int w    = threadIdx.x >> 5;
    const int lane = threadIdx.x & 31;
    const int wg   = blockIdx.x * P1W + w;
    if (wg >= BT4) return;
    const int b  = wg >> 6;
    const int t0 = (wg & 63) * 4;

    const int labl = y_true[b * L_DIM + lane];

    const float4* rp = reinterpret_cast<const float4*>(
        y_pred + ((size_t)b * T_DIM + t0) * C_DIM);

    float4 x[4];
#pragma unroll
    for (int j = 0; j < 4; ++j) x[j] = rp[(size_t)j * 32 + lane];

    float d[4], ez[4];
#pragma unroll
    for (int j = 0; j < 4; ++j) {
        float e0 = __expf(x[j].x), e1 = __expf(x[j].y);
        float e2 = __expf(x[j].z), e3 = __expf(x[j].w);
        reinterpret_cast<float4*>(esc[w][j])[lane] = make_float4(e0, e1, e2, e3);
        d[j]  = (e0 + e1) + (e2 + e3);
        ez[j] = e0;
    }
#pragma unroll
    for (int o = 16; o > 0; o >>= 1)
#pragma unroll
        for (int j = 0; j < 4; ++j)
            d[j] += __shfl_xor_sync(0xffffffffu, d[j], o);
    __syncwarp();

    float inv[4], p[4];
#pragma unroll
    for (int j = 0; j < 4; ++j) inv[j] = __fdividef(1.0f, d[j]);
#pragma unroll
    for (int j = 0; j < 4; ++j) p[j] = esc[w][j][labl] * inv[j];

    unsigned* gl = g_lab + ((size_t)b * (T_DIM / 2) + (t0 >> 1)) * L_DIM;
    __nv_bfloat162 p01 = __floats2bfloat162_rn(p[0], p[1]);
    __nv_bfloat162 p23 = __floats2bfloat162_rn(p[2], p[3]);
    gl[lane]         = *reinterpret_cast<unsigned*>(&p01);
    gl[L_DIM + lane] = *reinterpret_cast<unsigned*>(&p23);

    if (lane == 0) {
        __nv_bfloat162 b01 = __floats2bfloat162_rn(ez[0] * inv[0], ez[1] * inv[1]);
        __nv_bfloat162 b23 = __floats2bfloat162_rn(ez[2] * inv[2], ez[3] * inv[3]);
        uint2 pk;
        pk.x = *reinterpret_cast<unsigned*>(&b01);
        pk.y = *reinterpret_cast<unsigned*>(&b23);
        *reinterpret_cast<uint2*>(&g_blank[(size_t)b * T_DIM + t0]) = pk;
    }
}

// ---------------- pass 2: bidirectional alpha/beta --------------------------
__global__ __launch_bounds__(WPB2 * 32)
void ctc_pass2(const int* __restrict__ y_true,
               float* __restrict__ out, int B)
{
    __shared__ __nv_bfloat16 s_bl[WPB2][T_DIM];   // staged blank probs per row

    const int w    = threadIdx.x >> 5;
    const int lane = threadIdx.x & 31;
    const int b    = blockIdx.x * WPB2 + w;
    if (b >= B) return;
    const unsigned FULL = 0xffffffffu;

    const int labl = __ldg(&y_true[b * L_DIM + lane]);
    const int labp = __shfl_up_sync(FULL, labl, 1);
    const float m0 = (lane == 0) ? 0.f : 1.f;
    const float sk = (lane >= 1 && labl != labp) ? 1.f : 0.f;   // alpha skip s=2l+1
    float skn = __shfl_down_sync(FULL, sk, 1);                  // beta skip (lane l+1's)
    if (lane == 31) skn = 0.f;

    const unsigned*      gl = g_lab   + (size_t)b * (T_DIM / 2) * L_DIM;
    const __nv_bfloat16* gb = g_blank + (size_t)b * T_DIM;

    // stage this row's 256 blanks into smem (one coalesced uint4 per lane)
    reinterpret_cast<uint4*>(s_bl[w])[lane] =
        reinterpret_cast<const uint4*>(gb)[lane];
    __syncwarp();
    const __nv_bfloat16* bl = s_bl[w];

    // label-pair buffers: half-chunk = 8 pairs = 16 timesteps, double-buffered
    unsigned abuf[2][8], bbuf[2][8];
#pragma unroll
    for (int i = 0; i < 8; ++i) {
        abuf[0][i] = gl[(size_t)i * L_DIM + lane];           // pairs 0..7
        bbuf[0][i] = gl[(size_t)(120 + i) * L_DIM + lane];   // pairs 120..127
    }

    float a_e = (lane == 0) ? 1.f : 0.f;  // virtual alpha_{-1} = delta(s=0)
    float a_o = 0.f, a64 = 0.f, acca = 0.f;
    float b_e = 0.f, b_o = 0.f, b64 = 0.f, accb = 0.f;

#pragma unroll 1
    for (int h = 0; h < 8; ++h) {
        const int cb = h & 1, nx = cb ^ 1;
        if (h < 7) {
#pragma unroll
            for (int i = 0; i < 8; ++i) {
                abuf[nx][i] = gl[(size_t)((h + 1) * 8 + i) * L_DIM + lane];
                bbuf[nx][i] = gl[(size_t)((14 - h) * 8 + i) * L_DIM + lane];
            }
        }
#pragma unroll
        for (int u = 0; u < 8; ++u) {
            const int ta = 16 * h + 2 * u;          // alpha: t=ta, ta+1
            const int tb = 255 - 16 * h - 2 * u;    // beta:  t=tb, tb-1

            float2 pa = __bfloat1622float2(
                *reinterpret_cast<__nv_bfloat162*>(&abuf[cb][u]));
            float2 pb = __bfloat1622float2(
                *reinterpret_cast<__nv_bfloat162*>(&bbuf[cb][7 - u]));
            float abl0 = __bfloat162float(bl[ta]);
            float abl1 = __bfloat162float(bl[ta + 1]);
            float bbl0 = __bfloat162float(bl[tb]);
            float bbl1 = __bfloat162float(bl[tb - 1]);

            // ---- alpha step t=ta ----
            {
                float um = __shfl_up_sync(FULL, a_o, 1) * m0;
                float ae = (a_e + um) * abl0;
                float ao = ((a_o + a_e) + sk * um) * pa.x;
                a64 = (a64 + a_o) * abl0;           // valid on lane 31
                a_e = ae; a_o = ao;
            }
            // ---- beta step t=tb (pb.y) ----
            if (u == 0 && h == 0) {
                // init at t=255: beta_255[63]=p[lab31], beta_255[64]=blank
                b_o = (lane == 31) ? pb.y : 0.f;
                b64 = bbl0;
                b_e = 0.f;
            } else {
                float nbe = __shfl_down_sync(FULL, b_e, 1);
                float nbo = __shfl_down_sync(FULL, b_o, 1);
                nbe = (lane == 31) ? b64 : nbe;
                nbo = (lane == 31) ? 0.f : nbo;
                float be = (b_e + b_o) * bbl0;
                float bo = ((b_o + nbe) + skn * nbo) * pb.y;
                b64 = b64 * bbl0;
                b_e = be; b_o = bo;
            }
            // ---- alpha step t=ta+1 ----
            {
                float um = __shfl_up_sync(FULL, a_o, 1) * m0;
                float ae = (a_e + um) * abl1;
                float ao = ((a_o + a_e) + sk * um) * pa.y;
                a64 = (a64 + a_o) * abl1;
                a_e = ae; a_o = ao;
            }
            // ---- beta step t=tb-1 (pb.x) ----
            {
                float nbe = __shfl_down_sync(FULL, b_e, 1);
                float nbo = __shfl_down_sync(FULL, b_o, 1);
                nbe = (lane == 31) ? b64 : nbe;
                nbo = (lane == 31) ? 0.f : nbo;
                float be = (b_e + b_o) * bbl1;
                float bo = ((b_o + nbe) + skn * nbo) * pb.x;
                b64 = b64 * bbl1;
                b_e = be; b_o = bo;
            }

            // renorm both chains every 8 timesteps (chains overlap each other)
            if (u == 3 || u == 7) {
                float psa = a_e + a_o + ((lane == 31) ? a64 : 0.f);
                float psb = b_e + b_o + ((lane == 0)  ? b64 : 0.f);
#pragma unroll
                for (int o = 16; o > 0; o >>= 1) {
                    psa += __shfl_xor_sync(FULL, psa, o);
                    psb += __shfl_xor_sync(FULL, psb, o);
                }
                float ra = __fdividef(1.0f, psa);
                float rb = __fdividef(1.0f, psb);
                a_e *= ra; a_o *= ra; a64 *= ra;
                b_e *= rb; b_o *= rb; b64 *= rb;
                acca += __logf(psa);
                accb += __logf(psb);
            }
        }
    }

    // combine at the t=127 | t=128 seam:
    // P = sum_s alphapre_128[s] * beta_128[s]  (alphapre = transition-only)
    float um = __shfl_up_sync(FULL, a_o, 1) * m0;
    float apre_e = a_e + um;
    float apre_o = (a_o + a_e) + sk * um;
    float dot = apre_e * b_e + apre_o * b_o;
    if (lane == 31) dot += (a64 + a_o) * b64;     // state 64 (pre: stay + from 63)
#pragma unroll
    for (int o = 16; o > 0; o >>= 1)
        dot += __shfl_xor_sync(FULL, dot, o);

    if (lane == 0)
        out[b] = -(__logf(dot) + acca + accb);
}

extern "C" void kernel_launch(void* const* d_in, const int* in_sizes, int n_in,
                              void* d_out, int out_size)
{
    const int B = out_size;
    const int*   y_true;
    const float* y_pred;
    if (in_sizes[0] < in_sizes[1]) {       // labels buffer is the smaller one
        y_true = (const int*)d_in[0];
        y_pred = (const float*)d_in[1];
    } else {
        y_true = (const int*)d_in[1];
        y_pred = (const float*)d_in[0];
    }
    float* outp = (float*)d_out;

    const int BT4 = B * (T_DIM / 4);
    ctc_pass1<<<(BT4 + P1W - 1) / P1W, P1W * 32>>>(y_true, y_pred, BT4);
    ctc_pass2<<<(B + WPB2 - 1) / WPB2, WPB2 * 32>>>(y_true, outp, B);
}

// round 12
// speedup vs baseline: 1.0935x; 1.0028x over previous
#include <cuda_runtime.h>
#include <cuda_bf16.h>
#include <cstdint>

// CTC loss, two-pass.
// Pass 1: warp per 4 timesteps, softmax C=128, compact bf16 probs
//   (labels t-paired [b][t/2][32], blanks [b][t]).
// Pass 2: TWO warps per row. Warp A runs alpha over t=0..127. Warp B runs
//   beta over t=255..128 AS AN ALPHA on the reversed problem (labels
//   reversed, time reversed, s <-> 64-s). Combine: loss =
//   -log( sum_s alphapre_128[s] * beta_128[s] ) - renorm logs.
#define T_DIM 256
#define C_DIM 128
#define L_DIM 32
#define MAXB  2048
#define P1W   8
#define RPB   4          // rows per block, pass 2 (8 warps)

__device__ unsigned      g_lab[(size_t)MAXB * (T_DIM / 2) * L_DIM];
__device__ __nv_bfloat16 g_blank[(size_t)MAXB * T_DIM];

// ---------------- pass 1 (unchanged) ----------------------------------------
__global__ __launch_bounds__(P1W * 32)
void ctc_pass1(const int* __restrict__ y_true,
               const float* __restrict__ y_pred, int BT4)
{
    __shared__ float esc[P1W][4][C_DIM];

    const int w    = threadIdx.x >> 5;
    const int lane = threadIdx.x & 31;
    const int wg   = blockIdx.x * P1W + w;
    if (wg >= BT4) return;
    const int b  = wg >> 6;
    const int t0 = (wg & 63) * 4;

    const int labl = y_true[b * L_DIM + lane];

    const float4* rp = reinterpret_cast<const float4*>(
        y_pred + ((size_t)b * T_DIM + t0) * C_DIM);

    float4 x[4];
#pragma unroll
    for (int j = 0; j < 4; ++j) x[j] = rp[(size_t)j * 32 + lane];

    float d[4], ez[4];
#pragma unroll
    for (int j = 0; j < 4; ++j) {
        float e0 = __expf(x[j].x), e1 = __expf(x[j].y);
        float e2 = __expf(x[j].z), e3 = __expf(x[j].w);
        reinterpret_cast<float4*>(esc[w][j])[lane] = make_float4(e0, e1, e2, e3);
        d[j]  = (e0 + e1) + (e2 + e3);
        ez[j] = e0;
    }
#pragma unroll
    for (int o = 16; o > 0; o >>= 1)
#pragma unroll
        for (int j = 0; j < 4; ++j)
            d[j] += __shfl_xor_sync(0xffffffffu, d[j], o);
    __syncwarp();

    float inv[4], p[4];
#pragma unroll
    for (int j = 0; j < 4; ++j) inv[j] = __fdividef(1.0f, d[j]);
#pragma unroll
    for (int j = 0; j < 4; ++j) p[j] = esc[w][j][labl] * inv[j];

    unsigned* gl = g_lab + ((size_t)b * (T_DIM / 2) + (t0 >> 1)) * L_DIM;
    __nv_bfloat162 p01 = __floats2bfloat162_rn(p[0], p[1]);
    __nv_bfloat162 p23 = __floats2bfloat162_rn(p[2], p[3]);
    gl[lane]         = *reinterpret_cast<unsigned*>(&p01);
    gl[L_DIM + lane] = *reinterpret_cast<unsigned*>(&p23);

    if (lane == 0) {
        __nv_bfloat162 b01 = __floats2bfloat162_rn(ez[0] * inv[0], ez[1] * inv[1]);
        __nv_bfloat162 b23 = __floats2bfloat162_rn(ez[2] * inv[2], ez[3] * inv[3]);
        uint2 pk;
        pk.x = *reinterpret_cast<unsigned*>(&b01);
        pk.y = *reinterpret_cast<unsigned*>(&b23);
        *reinterpret_cast<uint2*>(&g_blank[(size_t)b * T_DIM + t0]) = pk;
    }
}

// ---------------- pass 2: alpha warp + beta warp per row ---------------------
__global__ __launch_bounds__(RPB * 2 * 32)
void ctc_pass2(const int* __restrict__ y_true,
               float* __restrict__ out, int B)
{
    __shared__ float         s_pre[RPB][66];   // alphapre_128
    __shared__ float         s_bet[RPB][66];   // beta_128 (original s coords)
    __shared__ float         s_acc[RPB][2];    // renorm logs (alpha, beta)
    __shared__ __nv_bfloat16 s_bl[RPB][T_DIM]; // staged blanks

    const int w    = threadIdx.x >> 5;         // 0..7
    const int lane = threadIdx.x & 31;
    const int r    = w >> 1;                   // row within block
    const int rev  = w & 1;                    // 0 = alpha warp, 1 = beta warp
    const int b    = blockIdx.x * RPB + r;
    const unsigned FULL = 0xffffffffu;
    const bool valid = (b < B);

    // labels in this warp's direction; skip mask computed on the (possibly
    // reversed) label order — reversal symmetry makes this exactly beta.
    int labl = 0;
    if (valid) labl = __ldg(&y_true[b * L_DIM + (rev ? 31 - lane : lane)]);
    const int   labp = __shfl_up_sync(FULL, labl, 1);
    const float m0   = (lane == 0) ? 0.f : 1.f;
    const float sk   = (lane >= 1 && labl != labp) ? 1.f : 0.f;

    const unsigned*      gl = g_lab   + (size_t)b * (T_DIM / 2) * L_DIM;
    const __nv_bfloat16* gb = g_blank + (size_t)b * T_DIM;
    const int col = rev ? (31 - lane) : lane;

    if (valid && !rev)      // stage row's 256 blanks (one uint4 per lane)
        reinterpret_cast<uint4*>(s_bl[r])[lane] =
            reinterpret_cast<const uint4*>(gb)[lane];
    __syncthreads();
    const __nv_bfloat16* bl = s_bl[r];

    float a_e = (lane == 0) ? 1.f : 0.f;   // virtual alpha_{-1} = delta(s=0)
    float a_o = 0.f, a64 = 0.f, acc = 0.f;

    if (valid) {
        // double-buffered pair loads, 8 pairs (16 steps) per group
        unsigned buf[2][8];
#pragma unroll
        for (int i = 0; i < 8; ++i)
            buf[0][i] = gl[(size_t)(rev ? 127 - i : i) * L_DIM + col];

#pragma unroll 1
        for (int h = 0; h < 8; ++h) {
            const int cb = h & 1, nx = cb ^ 1;
            if (h < 7) {
#pragma unroll
                for (int i = 0; i < 8; ++i) {
                    int q = (h + 1) * 8 + i;
                    buf[nx][i] = gl[(size_t)(rev ? 127 - q : q) * L_DIM + col];
                }
            }
#pragma unroll
            for (int i = 0; i < 8; ++i) {
                const int q  = h * 8 + i;                 // pair index (this dir)
                float2 pr = __bfloat1622float2(
                    *reinterpret_cast<__nv_bfloat162*>(&buf[cb][i]));
                const float p0 = rev ? pr.y : pr.x;
                const float p1 = rev ? pr.x : pr.y;
                const int t0 = rev ? (255 - 2 * q) : (2 * q);
                const int t1 = rev ? (254 - 2 * q) : (2 * q + 1);
                const float bt0 = __bfloat162float(bl[t0]);
                const float bt1 = __bfloat162float(bl[t1]);

                // two recursion steps (1 shfl each)
                {
                    float um = __shfl_up_sync(FULL, a_o, 1) * m0;
                    float ae = (a_e + um) * bt0;
                    float ao = ((a_o + a_e) + sk * um) * p0;
                    a64 = (a64 + a_o) * bt0;              // valid lane 31
                    a_e = ae; a_o = ao;
                }
                {
                    float um = __shfl_up_sync(FULL, a_o, 1) * m0;
                    float ae = (a_e + um) * bt1;
                    float ao = ((a_o + a_e) + sk * um) * p1;
                    a64 = (a64 + a_o) * bt1;
                    a_e = ae; a_o = ao;
                }

                if ((i & 3) == 3) {                       // renorm every 8 steps
                    float ps = a_e + a_o + ((lane == 31) ? a64 : 0.f);
#pragma unroll
                    for (int o = 16; o > 0; o >>= 1)
                        ps += __shfl_xor_sync(FULL, ps, o);
                    float rr = __fdividef(1.0f, ps);
                    a_e *= rr; a_o *= rr; a64 *= rr;
                    acc += __logf(ps);
                }
            }
        }

        if (!rev) {
            // alphapre_128: transitions only (no emission)
            float um = __shfl_up_sync(FULL, a_o, 1) * m0;
            s_pre[r][2 * lane]     = a_e + um;
            s_pre[r][2 * lane + 1] = (a_o + a_e) + sk * um;
            if (lane == 31) s_pre[r][64] = a64 + a_o;
            if (lane == 0)  s_acc[r][0] = acc;
        } else {
            // beta_128[s] = alpha'_127[64-s]: un-reverse state coords
            s_bet[r][64 - 2 * lane] = a_e;
            s_bet[r][63 - 2 * lane] = a_o;
            if (lane == 31) s_bet[r][0] = a64;
            if (lane == 0)  s_acc[r][1] = acc;
        }
    }
    __syncthreads();

    if (valid && !rev) {
        float dot = s_pre[r][2 * lane]     * s_bet[r][2 * lane]
                  + s_pre[r][2 * lane + 1] * s_bet[r][2 * lane + 1];
        if (lane == 0) dot += s_pre[r][64] * s_bet[r][64];
#pragma unroll
        for (int o = 16; o > 0; o >>= 1)
            dot += __shfl_xor_sync(FULL, dot, o);
        if (lane == 0)
            out[b] = -(__logf(dot) + s_acc[r][0] + s_acc[r][1]);
    }
}

extern "C" void kernel_launch(void* const* d_in, const int* in_sizes, int n_in,
                              void* d_out, int out_size)
{
    const int B = out_size;
    const int*   y_true;
    const float* y_pred;
    if (in_sizes[0] < in_sizes[1]) {       // labels buffer is the smaller one
        y_true = (const int*)d_in[0];
        y_pred = (const float*)d_in[1];
    } else {
        y_true = (const int*)d_in[1];
        y_pred = (const float*)d_in[0];
    }
    float* outp = (float*)d_out;

    const int BT4 = B * (T_DIM / 4);
    ctc_pass1<<<(BT4 + P1W - 1) / P1W, P1W * 32>>>(y_true, y_pred, BT4);
    ctc_pass2<<<(B + RPB - 1) / RPB, RPB * 2 * 32>>>(y_true, outp, B);
}